// round 1
// baseline (speedup 1.0000x reference)
#include <cuda_runtime.h>
#include <math.h>

// Problem constants
#define BB     4
#define TT     2048
#define DM     1024
#define QKD    1024
#define VD     2048
#define NH     8
#define DK     128     // per-head qk dim
#define DV     256     // per-head v dim
#define CHUNK  128
#define NCHUNK 16
#define ROWS   (BB*TT)   // 8192
#define QKVC   (2*QKD + VD)  // 4096
#define STATE  (DK*DV)   // 32768

// ---------------- scratch (global __device__ arrays; no allocation) ----------
__device__ float g_qkv [ (size_t)ROWS * QKVC ];      // 134 MB
__device__ float g_gate[ (size_t)ROWS * VD   ];      // 67 MB
__device__ float g_kvc [ (size_t)32 * NCHUNK * STATE ]; // per-chunk KV contributions
__device__ float g_sin [ (size_t)32 * NCHUNK * STATE ]; // state entering each chunk
__device__ float g_O   [ (size_t)32 * TT * DV ];     // retention output [bh][t][dv]
__device__ float g_Y   [ (size_t)ROWS * VD   ];      // gated normed

// ---------------- generic 128x128 SGEMM, BK=8, 8x8 per thread ----------------
__global__ __launch_bounds__(256) void sgemm128(
    const float* __restrict__ A, const float* __restrict__ B,
    float* __restrict__ C, int M, int N, int K, int do_silu)
{
    __shared__ float As[8][132];  // transposed A tile, padded
    __shared__ float Bs[8][128];
    int tid = threadIdx.x;
    int bx = blockIdx.x, by = blockIdx.y;
    int tx = tid & 15, ty = tid >> 4;
    int a_row = tid >> 1, a_col = (tid & 1) * 4;
    int b_row = tid >> 5, b_col = (tid & 31) * 4;
    const float* Ap = A + (size_t)(by*128 + a_row)*K + a_col;
    const float* Bp = B + (size_t)b_row*N + (size_t)bx*128 + b_col;

    float acc[8][8];
    #pragma unroll
    for (int i = 0; i < 8; i++)
        #pragma unroll
        for (int j = 0; j < 8; j++) acc[i][j] = 0.f;

    for (int k0 = 0; k0 < K; k0 += 8) {
        float4 av = *(const float4*)(Ap + k0);
        float4 bv = *(const float4*)(Bp + (size_t)k0*N);
        As[a_col+0][a_row] = av.x;
        As[a_col+1][a_row] = av.y;
        As[a_col+2][a_row] = av.z;
        As[a_col+3][a_row] = av.w;
        *(float4*)&Bs[b_row][b_col] = bv;
        __syncthreads();
        #pragma unroll
        for (int k = 0; k < 8; k++) {
            float af[8], bf[8];
            #pragma unroll
            for (int i = 0; i < 8; i++) af[i] = As[k][ty*8 + i];
            #pragma unroll
            for (int j = 0; j < 8; j++) bf[j] = Bs[k][tx + 16*j];
            #pragma unroll
            for (int i = 0; i < 8; i++)
                #pragma unroll
                for (int j = 0; j < 8; j++)
                    acc[i][j] += af[i] * bf[j];
        }
        __syncthreads();
    }
    #pragma unroll
    for (int i = 0; i < 8; i++) {
        float* cp = C + (size_t)(by*128 + ty*8 + i)*N + (size_t)bx*128;
        #pragma unroll
        for (int j = 0; j < 8; j++) {
            float v = acc[i][j];
            if (do_silu) v = v / (1.f + expf(-v));
            cp[tx + 16*j] = v;
        }
    }
}

// ---------------- xPos rotary on q (cols 0..1023) and k (1024..2047) ----------
// Also folds dk^{-1/2} into q.
__global__ void rotary_kernel(float* __restrict__ qkv)
{
    int row = blockIdx.x;               // b*T + t
    int t   = row & (TT - 1);
    int j   = blockIdx.y * 256 + threadIdx.x;   // 0..511
    if (j >= 512) return;

    float base = (2.f*(float)j + 0.4f*1024.f) * (1.f/(1.4f*1024.f));
    float sc = expf(((float)t * (1.f/512.f)) * logf(base));
    float inv_freq = expf(-(float)j * (1.f/512.f) * logf(10000.f));
    float ang = (float)t * inv_freq;
    float sn, cs;
    sincosf(ang, &sn, &cs);

    float* p = qkv + (size_t)row * QKVC;
    const float rs = 0.08838834764831845f;  // 1/sqrt(128)

    float qe = p[2*j], qo = p[2*j+1];
    float cq = cs*sc, sq = sn*sc;
    p[2*j]   = (qe*cq - qo*sq) * rs;
    p[2*j+1] = (qo*cq + qe*sq) * rs;

    float ke = p[QKD + 2*j], ko = p[QKD + 2*j+1];
    float ci = cs/sc, si = sn/sc;
    p[QKD + 2*j]   = ke*ci - ko*si;
    p[QKD + 2*j+1] = ko*ci + ke*si;
}

// ---------------- Pass A: per-chunk KV_c = sum_tau decay^{127-tau} k_tau v_tau^T
__global__ __launch_bounds__(512) void pass_a(
    const float* __restrict__ qkv, const float* __restrict__ decay)
{
    __shared__ float Ks[16*128];
    __shared__ float Vs[16*256];
    __shared__ float dpow[128];
    int blk = blockIdx.x;
    int c = blk & 15, bh = blk >> 4;
    int b = bh >> 3, h = bh & 7;
    int tid = threadIdx.x;
    float dec = decay[h];
    for (int i = tid; i < 128; i += 512) dpow[i] = powf(dec, (float)(127 - i));
    __syncthreads();

    int gi = tid >> 5;  // dk rows gi*8..+7
    int gj = tid & 31;  // dv cols gj + 32*j

    float acc[8][8];
    #pragma unroll
    for (int i = 0; i < 8; i++)
        #pragma unroll
        for (int j = 0; j < 8; j++) acc[i][j] = 0.f;

    const float* Kb = qkv + ((size_t)(b*TT) + (size_t)c*CHUNK)*QKVC + QKD + h*DK;
    const float* Vb = qkv + ((size_t)(b*TT) + (size_t)c*CHUNK)*QKVC + 2*QKD + h*DV;

    for (int t0 = 0; t0 < 128; t0 += 16) {
        for (int u = tid; u < 16*128; u += 512) {
            int tt = u >> 7, d = u & 127;
            Ks[u] = dpow[t0 + tt] * Kb[(size_t)(t0 + tt)*QKVC + d];
        }
        for (int u = tid; u < 16*256; u += 512) {
            int tt = u >> 8, d = u & 255;
            Vs[u] = Vb[(size_t)(t0 + tt)*QKVC + d];
        }
        __syncthreads();
        #pragma unroll
        for (int tt = 0; tt < 16; tt++) {
            float a[8], bb[8];
            #pragma unroll
            for (int i = 0; i < 8; i++) a[i] = Ks[tt*128 + gi*8 + i];
            #pragma unroll
            for (int j = 0; j < 8; j++) bb[j] = Vs[tt*256 + gj + 32*j];
            #pragma unroll
            for (int i = 0; i < 8; i++)
                #pragma unroll
                for (int j = 0; j < 8; j++)
                    acc[i][j] += a[i] * bb[j];
        }
        __syncthreads();
    }
    float* out = g_kvc + ((size_t)bh*NCHUNK + c)*STATE;
    #pragma unroll
    for (int i = 0; i < 8; i++)
        #pragma unroll
        for (int j = 0; j < 8; j++)
            out[(size_t)(gi*8 + i)*DV + gj + 32*j] = acc[i][j];
}

// ---------------- Scan: S_in[c] and curr_kv (= final state) ------------------
__global__ void scan_k(float* __restrict__ curr_kv, const float* __restrict__ decay)
{
    int bh = blockIdx.x >> 7;
    int e  = ((blockIdx.x & 127) << 8) + threadIdx.x;
    float dC = powf(decay[bh & 7], 128.f);
    size_t base = (size_t)bh * NCHUNK * STATE;
    float s = 0.f;
    #pragma unroll
    for (int c = 0; c < NCHUNK; c++) {
        g_sin[base + (size_t)c*STATE + e] = s;
        s = s*dC + g_kvc[base + (size_t)c*STATE + e];
    }
    curr_kv[(size_t)bh*STATE + e] = s;
}

// ---------------- Pass B: O = mask(QK^T)V + diag(decay^{tau+1}) Q S_in -------
__global__ __launch_bounds__(512, 1) void pass_b(
    const float* __restrict__ qkv, const float* __restrict__ decay)
{
    extern __shared__ float sm[];
    float* dpow = sm;                 // 128
    float* As   = sm + 128;           // 128*129
    float* Ta   = As + 128*129;       // 2048
    float* Tb   = Ta + 2048;          // 4096

    int blk = blockIdx.x;
    int c = blk & 15, bh = blk >> 4;
    int b = bh >> 3, h = bh & 7;
    int tid = threadIdx.x;
    float dec = decay[h];
    for (int i = tid; i < 128; i += 512) dpow[i] = powf(dec, (float)i);

    int gi = tid >> 5;  // t rows gi*8..+7
    int gj = tid & 31;  // cols strided: gj + 32*j

    const float* Qb = qkv + ((size_t)(b*TT) + (size_t)c*CHUNK)*QKVC + h*DK;
    const float* Kb = Qb + QKD;
    const float* Vb = qkv + ((size_t)(b*TT) + (size_t)c*CHUNK)*QKVC + 2*QKD + h*DV;

    // ---- Stage 1: A = Q K^T with decay mask -> As ----
    {
        float acc1[8][4];
        #pragma unroll
        for (int i = 0; i < 8; i++)
            #pragma unroll
            for (int j = 0; j < 4; j++) acc1[i][j] = 0.f;

        for (int k0 = 0; k0 < 128; k0 += 16) {
            for (int u = tid; u < 2048; u += 512) {
                int t = u >> 4, kk = u & 15;
                Ta[kk*128 + t] = Qb[(size_t)t*QKVC + k0 + kk];
                Tb[kk*128 + t] = Kb[(size_t)t*QKVC + k0 + kk];
            }
            __syncthreads();
            #pragma unroll
            for (int kk = 0; kk < 16; kk++) {
                float a[8], bb[4];
                #pragma unroll
                for (int i = 0; i < 8; i++) a[i] = Ta[kk*128 + gi*8 + i];
                #pragma unroll
                for (int j = 0; j < 4; j++) bb[j] = Tb[kk*128 + gj + 32*j];
                #pragma unroll
                for (int i = 0; i < 8; i++)
                    #pragma unroll
                    for (int j = 0; j < 4; j++)
                        acc1[i][j] += a[i] * bb[j];
            }
            __syncthreads();
        }
        #pragma unroll
        for (int i = 0; i < 8; i++) {
            int t = gi*8 + i;
            #pragma unroll
            for (int j = 0; j < 4; j++) {
                int s = gj + 32*j;
                As[t*129 + s] = (t >= s) ? acc1[i][j] * dpow[t - s] : 0.f;
            }
        }
    }
    __syncthreads();

    // ---- Stage 2a: acc = Q @ S_in ----
    float acc[8][8];
    #pragma unroll
    for (int i = 0; i < 8; i++)
        #pragma unroll
        for (int j = 0; j < 8; j++) acc[i][j] = 0.f;

    const float* Sc = g_sin + ((size_t)bh*NCHUNK + c)*STATE;
    for (int k0 = 0; k0 < 128; k0 += 16) {
        for (int u = tid; u < 2048; u += 512) {
            int t = u >> 4, kk = u & 15;
            Ta[kk*128 + t] = Qb[(size_t)t*QKVC + k0 + kk];
        }
        for (int u = tid; u < 4096; u += 512) {
            int kk = u >> 8, v = u & 255;
            Tb[kk*256 + v] = Sc[(size_t)(k0 + kk)*DV + v];
        }
        __syncthreads();
        #pragma unroll
        for (int kk = 0; kk < 16; kk++) {
            float a[8], bb[8];
            #pragma unroll
            for (int i = 0; i < 8; i++) a[i] = Ta[kk*128 + gi*8 + i];
            #pragma unroll
            for (int j = 0; j < 8; j++) bb[j] = Tb[kk*256 + gj + 32*j];
            #pragma unroll
            for (int i = 0; i < 8; i++)
                #pragma unroll
                for (int j = 0; j < 8; j++)
                    acc[i][j] += a[i] * bb[j];
        }
        __syncthreads();
    }
    // scale rows by decay^{tau+1}
    #pragma unroll
    for (int i = 0; i < 8; i++) {
        float f = dpow[gi*8 + i] * dec;
        #pragma unroll
        for (int j = 0; j < 8; j++) acc[i][j] *= f;
    }

    // ---- Stage 2b: acc += As @ V ----
    for (int s0 = 0; s0 < 128; s0 += 16) {
        for (int u = tid; u < 4096; u += 512) {
            int ss = u >> 8, v = u & 255;
            Tb[ss*256 + v] = Vb[(size_t)(s0 + ss)*QKVC + v];
        }
        __syncthreads();
        #pragma unroll
        for (int ss = 0; ss < 16; ss++) {
            float a[8], bb[8];
            #pragma unroll
            for (int i = 0; i < 8; i++) a[i] = As[(gi*8 + i)*129 + s0 + ss];
            #pragma unroll
            for (int j = 0; j < 8; j++) bb[j] = Tb[ss*256 + gj + 32*j];
            #pragma unroll
            for (int i = 0; i < 8; i++)
                #pragma unroll
                for (int j = 0; j < 8; j++)
                    acc[i][j] += a[i] * bb[j];
        }
        __syncthreads();
    }

    float* Op = g_O + ((size_t)bh*TT + (size_t)c*CHUNK)*DV;
    #pragma unroll
    for (int i = 0; i < 8; i++)
        #pragma unroll
        for (int j = 0; j < 8; j++)
            Op[(size_t)(gi*8 + i)*DV + gj + 32*j] = acc[i][j];
}

// ---------------- GroupNorm(256 per head) + silu-gate multiply ---------------
__global__ void norm_gate(void)
{
    int row = blockIdx.x;            // b*T + t
    int b = row >> 11, t = row & (TT - 1);
    int h = threadIdx.x >> 5, lane = threadIdx.x & 31;

    const float* op = g_O + (((size_t)(b*NH + h))*TT + t)*DV;
    float x[8];
    float s = 0.f;
    #pragma unroll
    for (int i = 0; i < 8; i++) { x[i] = op[lane + 32*i]; s += x[i]; }
    #pragma unroll
    for (int o = 16; o > 0; o >>= 1) s += __shfl_xor_sync(0xffffffffu, s, o);
    float mu = s * (1.f/256.f);
    float v = 0.f;
    #pragma unroll
    for (int i = 0; i < 8; i++) { float d = x[i] - mu; v += d*d; }
    #pragma unroll
    for (int o = 16; o > 0; o >>= 1) v += __shfl_xor_sync(0xffffffffu, v, o);
    float r = rsqrtf(v * (1.f/256.f) + 1e-5f);

    const float* gp = g_gate + (size_t)row*VD + h*DV;
    float* yp = g_Y + (size_t)row*VD + h*DV;
    #pragma unroll
    for (int i = 0; i < 8; i++)
        yp[lane + 32*i] = gp[lane + 32*i] * (x[i] - mu) * r;
}

// ---------------- launch -----------------------------------------------------
extern "C" void kernel_launch(void* const* d_in, const int* in_sizes, int n_in,
                              void* d_out, int out_size)
{
    (void)in_sizes; (void)n_in; (void)out_size;
    const float* X     = (const float*)d_in[0];
    const float* Wqkv  = (const float*)d_in[1];
    const float* Wg    = (const float*)d_in[2];
    const float* Wproj = (const float*)d_in[3];
    const float* decay = (const float*)d_in[4];
    float* out = (float*)d_out;
    float* curr_kv = out + (size_t)ROWS * DM;   // proj_out first, then curr_kv

    float *qkv, *gate, *Y;
    cudaGetSymbolAddress((void**)&qkv,  g_qkv);
    cudaGetSymbolAddress((void**)&gate, g_gate);
    cudaGetSymbolAddress((void**)&Y,    g_Y);

    const int smemB = (128 + 128*129 + 2048 + 4096) * 4;  // 91136 B
    cudaFuncSetAttribute(pass_b, cudaFuncAttributeMaxDynamicSharedMemorySize, smemB);

    // 1) QKV = X @ W_qkv
    sgemm128<<<dim3(QKVC/128, ROWS/128), 256>>>(X, Wqkv, qkv, ROWS, QKVC, DM, 0);
    // 2) gate = silu(X @ W_g)
    sgemm128<<<dim3(VD/128, ROWS/128), 256>>>(X, Wg, gate, ROWS, VD, DM, 1);
    // 3) rotary (xPos) on q,k in place; folds dk^-0.5 into q
    rotary_kernel<<<dim3(ROWS, 2), 256>>>(qkv);
    // 4) per-chunk KV contributions
    pass_a<<<32*NCHUNK, 512>>>(qkv, decay);
    // 5) state scan -> S_in + curr_kv output
    scan_k<<<32*128, 256>>>(curr_kv, decay);
    // 6) intra-chunk + cross-chunk retention output
    pass_b<<<32*NCHUNK, 512, smemB>>>(qkv, decay);
    // 7) groupnorm + gate
    norm_gate<<<ROWS, 256>>>();
    // 8) proj_out = Y @ W_proj
    sgemm128<<<dim3(DM/128, ROWS/128), 256>>>(Y, Wproj, out, ROWS, DM, VD, 0);
}

// round 3
// speedup vs baseline: 1.9497x; 1.9497x over previous
#include <cuda_runtime.h>
#include <cuda_bf16.h>
#include <math.h>
#include <stdint.h>

// Problem constants
#define BB     4
#define TT     2048
#define DM     1024
#define QKD    1024
#define VD     2048
#define NH     8
#define DK     128
#define DV     256
#define CHUNK  128
#define NCHUNK 16
#define ROWS   (BB*TT)       // 8192
#define QKVC   (2*QKD + VD)  // 4096
#define STATE  (DK*DV)       // 32768

// ---------------- scratch (global __device__ arrays; no allocation) ----------
__device__ float g_qkv [ (size_t)ROWS * QKVC ];
__device__ float g_gate[ (size_t)ROWS * VD   ];
__device__ float g_kvc [ (size_t)32 * NCHUNK * STATE ];
__device__ float g_sin [ (size_t)32 * NCHUNK * STATE ];
__device__ float g_O   [ (size_t)32 * TT * DV ];

// split-bf16 operand buffers
__device__ __nv_bfloat16 g_xh [ (size_t)ROWS * DM ];
__device__ __nv_bfloat16 g_xl [ (size_t)ROWS * DM ];
__device__ __nv_bfloat16 g_wqh[ (size_t)QKVC * DM ];   // W_qkv^T [4096,1024]
__device__ __nv_bfloat16 g_wql[ (size_t)QKVC * DM ];
__device__ __nv_bfloat16 g_wgh[ (size_t)VD * DM ];     // W_g^T
__device__ __nv_bfloat16 g_wgl[ (size_t)VD * DM ];
__device__ __nv_bfloat16 g_wph[ (size_t)DM * VD ];     // W_proj^T
__device__ __nv_bfloat16 g_wpl[ (size_t)DM * VD ];
__device__ __nv_bfloat16 g_yh [ (size_t)ROWS * VD ];
__device__ __nv_bfloat16 g_yl [ (size_t)ROWS * VD ];

// ======================= helpers =============================================
__device__ __forceinline__ uint32_t smem_u32(const void* p) {
    uint32_t a;
    asm("{ .reg .u64 t; cvta.to.shared.u64 t, %1; cvt.u32.u64 %0, t; }"
        : "=r"(a) : "l"(p));
    return a;
}
__device__ __forceinline__ void cpa16(uint32_t s, const void* g) {
    asm volatile("cp.async.cg.shared.global [%0], [%1], 16;" :: "r"(s), "l"(g));
}
#define CP_COMMIT() asm volatile("cp.async.commit_group;" ::: "memory")

__device__ __forceinline__ void ldm_x4(uint32_t* r, uint32_t addr) {
    asm volatile("ldmatrix.sync.aligned.m8n8.x4.shared.b16 {%0,%1,%2,%3}, [%4];"
        : "=r"(r[0]), "=r"(r[1]), "=r"(r[2]), "=r"(r[3]) : "r"(addr));
}
__device__ __forceinline__ void mma_bf16(float* c, const uint32_t* a,
                                         uint32_t b0, uint32_t b1) {
    asm volatile(
        "mma.sync.aligned.m16n8k16.row.col.f32.bf16.bf16.f32 "
        "{%0,%1,%2,%3}, {%4,%5,%6,%7}, {%8,%9}, {%0,%1,%2,%3};"
        : "+f"(c[0]), "+f"(c[1]), "+f"(c[2]), "+f"(c[3])
        : "r"(a[0]), "r"(a[1]), "r"(a[2]), "r"(a[3]), "r"(b0), "r"(b1));
}

// ======================= split / transpose-split kernels =====================
__global__ void split_kernel(const float4* __restrict__ in,
                             __nv_bfloat16* __restrict__ oh,
                             __nv_bfloat16* __restrict__ ol, size_t n4)
{
    size_t i = (size_t)blockIdx.x * blockDim.x + threadIdx.x;
    if (i >= n4) return;
    float4 v = in[i];
    __nv_bfloat16 h0 = __float2bfloat16(v.x), h1 = __float2bfloat16(v.y);
    __nv_bfloat16 h2 = __float2bfloat16(v.z), h3 = __float2bfloat16(v.w);
    __nv_bfloat162* oh2 = (__nv_bfloat162*)(oh + i*4);
    __nv_bfloat162* ol2 = (__nv_bfloat162*)(ol + i*4);
    oh2[0] = __nv_bfloat162(h0, h1);
    oh2[1] = __nv_bfloat162(h2, h3);
    ol2[0] = __nv_bfloat162(__float2bfloat16(v.x - __bfloat162float(h0)),
                            __float2bfloat16(v.y - __bfloat162float(h1)));
    ol2[1] = __nv_bfloat162(__float2bfloat16(v.z - __bfloat162float(h2)),
                            __float2bfloat16(v.w - __bfloat162float(h3)));
}

// in [K,N] fp32 -> out [N,K] bf16 hi/lo
__global__ void tsplit_kernel(const float* __restrict__ in,
                              __nv_bfloat16* __restrict__ oh,
                              __nv_bfloat16* __restrict__ ol, int K, int N)
{
    __shared__ float s[32][33];
    int k0 = blockIdx.y * 32, n0 = blockIdx.x * 32;
    for (int i = threadIdx.y; i < 32; i += 8)
        s[i][threadIdx.x] = in[(size_t)(k0 + i) * N + n0 + threadIdx.x];
    __syncthreads();
    for (int i = threadIdx.y; i < 32; i += 8) {
        float v = s[threadIdx.x][i];
        __nv_bfloat16 h = __float2bfloat16(v);
        size_t o = (size_t)(n0 + i) * K + k0 + threadIdx.x;
        oh[o] = h;
        ol[o] = __float2bfloat16(v - __bfloat162float(h));
    }
}

// ======================= mma.sync split-bf16 GEMM ============================
// C[M,N] = Ah*Bh + Ah*Bl + Al*Bh; A:[M,K] bf16 K-major, B:[N,K] bf16 K-major.
// CTA tile 128x128, BK=32, 8 warps (2x4), warp tile 64x32, double-buffered cp.async.
#define BM   128
#define BN   128
#define BKC  32
#define STRD 40                       // padded row stride in bf16 (80 B)
#define TSZ  (128*STRD)               // elems per buffer
#define STAGE_E (4*TSZ)               // Ah,Al,Bh,Bl
#define SMEM_GEMM (2*STAGE_E*2)       // bytes = 81920

__global__ __launch_bounds__(256) void gemm_mma(
    const __nv_bfloat16* __restrict__ Ah, const __nv_bfloat16* __restrict__ Al,
    const __nv_bfloat16* __restrict__ Bh, const __nv_bfloat16* __restrict__ Bl,
    float* __restrict__ C, int M, int N, int K, int do_silu)
{
    extern __shared__ char smem[];
    uint32_t sbase = smem_u32(smem);
    int tid = threadIdx.x, wid = tid >> 5, lane = tid & 31;
    int m0 = blockIdx.y * BM, n0 = blockIdx.x * BN;
    int wm = wid >> 2, wn = wid & 3;     // warp tile: rows wm*64, cols wn*32

    float acc[4][4][4];
    #pragma unroll
    for (int i = 0; i < 4; i++)
        #pragma unroll
        for (int j = 0; j < 4; j++)
            #pragma unroll
            for (int q = 0; q < 4; q++) acc[i][j][q] = 0.f;

    const int nch = K / BKC;
    const __nv_bfloat16* srcs[4] = {Ah, Al, Bh, Bl};

    // ---- async stage loader: 4 buffers x 512 segs (16B) = 8 cp.async/thread
    auto load_stage = [&](int c, int st) {
        size_t kb = (size_t)c * BKC;
        uint32_t so = sbase + (uint32_t)st * STAGE_E * 2;
        #pragma unroll
        for (int q = 0; q < 4; q++) {
            int base_row = (q < 2) ? m0 : n0;
            const __nv_bfloat16* src = srcs[q];
            #pragma unroll
            for (int it = 0; it < 2; it++) {
                int u = tid + it * 256;          // 0..511
                int r = u >> 2, sg = u & 3;
                cpa16(so + (uint32_t)q * TSZ * 2 + r * (STRD*2) + sg * 16,
                      src + (size_t)(base_row + r) * K + kb + sg * 8);
            }
        }
        CP_COMMIT();
    };

    load_stage(0, 0);

    for (int c = 0; c < nch; c++) {
        int st = c & 1;
        if (c + 1 < nch) {
            load_stage(c + 1, st ^ 1);
            asm volatile("cp.async.wait_group 1;" ::: "memory");
        } else {
            asm volatile("cp.async.wait_group 0;" ::: "memory");
        }
        __syncthreads();

        uint32_t so = sbase + (uint32_t)st * STAGE_E * 2;
        uint32_t aoff_h = so;
        uint32_t aoff_l = so + TSZ * 2;
        uint32_t boff_h = so + 2 * TSZ * 2;
        uint32_t boff_l = so + 3 * TSZ * 2;

        int arow = wm * 64 + (lane & 15);
        int brow = wn * 32 + (lane & 15);
        int colb = (lane >> 4) * 16;

        #pragma unroll
        for (int kf = 0; kf < 2; kf++) {
            uint32_t ah[4][4], al[4][4];
            #pragma unroll
            for (int mf = 0; mf < 4; mf++) {
                uint32_t ao = (uint32_t)(arow + mf * 16) * (STRD*2) + kf * 32 + colb;
                ldm_x4(ah[mf], aoff_h + ao);
                ldm_x4(al[mf], aoff_l + ao);
            }
            uint32_t bh[4][2], bl[4][2];
            #pragma unroll
            for (int pp = 0; pp < 2; pp++) {
                uint32_t bo = (uint32_t)(brow + pp * 16) * (STRD*2) + kf * 32 + colb;
                uint32_t r[4];
                ldm_x4(r, boff_h + bo);
                bh[pp*2][0] = r[0]; bh[pp*2][1] = r[2];
                bh[pp*2+1][0] = r[1]; bh[pp*2+1][1] = r[3];
                ldm_x4(r, boff_l + bo);
                bl[pp*2][0] = r[0]; bl[pp*2][1] = r[2];
                bl[pp*2+1][0] = r[1]; bl[pp*2+1][1] = r[3];
            }
            #pragma unroll
            for (int mf = 0; mf < 4; mf++)
                #pragma unroll
                for (int nf = 0; nf < 4; nf++) {
                    mma_bf16(acc[mf][nf], ah[mf], bh[nf][0], bh[nf][1]);
                    mma_bf16(acc[mf][nf], ah[mf], bl[nf][0], bl[nf][1]);
                    mma_bf16(acc[mf][nf], al[mf], bh[nf][0], bh[nf][1]);
                }
        }
        __syncthreads();
    }

    // ---- epilogue ----
    #pragma unroll
    for (int mf = 0; mf < 4; mf++) {
        int row = m0 + wm * 64 + mf * 16 + (lane >> 2);
        #pragma unroll
        for (int nf = 0; nf < 4; nf++) {
            int col = n0 + wn * 32 + nf * 8 + (lane & 3) * 2;
            float v0 = acc[mf][nf][0], v1 = acc[mf][nf][1];
            float v2 = acc[mf][nf][2], v3 = acc[mf][nf][3];
            if (do_silu) {
                v0 = v0 / (1.f + expf(-v0)); v1 = v1 / (1.f + expf(-v1));
                v2 = v2 / (1.f + expf(-v2)); v3 = v3 / (1.f + expf(-v3));
            }
            *(float2*)(C + (size_t)row * N + col)       = make_float2(v0, v1);
            *(float2*)(C + (size_t)(row + 8) * N + col) = make_float2(v2, v3);
        }
    }
}

// ---------------- xPos rotary on q,k; folds dk^{-1/2} into q ------------------
__global__ void rotary_kernel(float* __restrict__ qkv)
{
    int row = blockIdx.x;
    int t   = row & (TT - 1);
    int j   = blockIdx.y * 256 + threadIdx.x;
    if (j >= 512) return;

    float base = (2.f*(float)j + 0.4f*1024.f) * (1.f/(1.4f*1024.f));
    float sc = expf(((float)t * (1.f/512.f)) * logf(base));
    float inv_freq = expf(-(float)j * (1.f/512.f) * logf(10000.f));
    float ang = (float)t * inv_freq;
    float sn, cs;
    sincosf(ang, &sn, &cs);

    float* p = qkv + (size_t)row * QKVC;
    const float rs = 0.08838834764831845f;

    float qe = p[2*j], qo = p[2*j+1];
    float cq = cs*sc, sq = sn*sc;
    p[2*j]   = (qe*cq - qo*sq) * rs;
    p[2*j+1] = (qo*cq + qe*sq) * rs;

    float ke = p[QKD + 2*j], ko = p[QKD + 2*j+1];
    float ci = cs/sc, si = sn/sc;
    p[QKD + 2*j]   = ke*ci - ko*si;
    p[QKD + 2*j+1] = ko*ci + ke*si;
}

// ---------------- Pass A ------------------------------------------------------
__global__ __launch_bounds__(512) void pass_a(
    const float* __restrict__ qkv, const float* __restrict__ decay)
{
    __shared__ float Ks[16*128];
    __shared__ float Vs[16*256];
    __shared__ float dpow[128];
    int blk = blockIdx.x;
    int c = blk & 15, bh = blk >> 4;
    int b = bh >> 3, h = bh & 7;
    int tid = threadIdx.x;
    float dec = decay[h];
    for (int i = tid; i < 128; i += 512) dpow[i] = powf(dec, (float)(127 - i));
    __syncthreads();

    int gi = tid >> 5, gj = tid & 31;
    float acc[8][8];
    #pragma unroll
    for (int i = 0; i < 8; i++)
        #pragma unroll
        for (int j = 0; j < 8; j++) acc[i][j] = 0.f;

    const float* Kb = qkv + ((size_t)(b*TT) + (size_t)c*CHUNK)*QKVC + QKD + h*DK;
    const float* Vb = qkv + ((size_t)(b*TT) + (size_t)c*CHUNK)*QKVC + 2*QKD + h*DV;

    for (int t0 = 0; t0 < 128; t0 += 16) {
        for (int u = tid; u < 16*128; u += 512) {
            int tt = u >> 7, d = u & 127;
            Ks[u] = dpow[t0 + tt] * Kb[(size_t)(t0 + tt)*QKVC + d];
        }
        for (int u = tid; u < 16*256; u += 512) {
            int tt = u >> 8, d = u & 255;
            Vs[u] = Vb[(size_t)(t0 + tt)*QKVC + d];
        }
        __syncthreads();
        #pragma unroll
        for (int tt = 0; tt < 16; tt++) {
            float a[8], bb[8];
            #pragma unroll
            for (int i = 0; i < 8; i++) a[i] = Ks[tt*128 + gi*8 + i];
            #pragma unroll
            for (int j = 0; j < 8; j++) bb[j] = Vs[tt*256 + gj + 32*j];
            #pragma unroll
            for (int i = 0; i < 8; i++)
                #pragma unroll
                for (int j = 0; j < 8; j++)
                    acc[i][j] += a[i] * bb[j];
        }
        __syncthreads();
    }
    float* out = g_kvc + ((size_t)bh*NCHUNK + c)*STATE;
    #pragma unroll
    for (int i = 0; i < 8; i++)
        #pragma unroll
        for (int j = 0; j < 8; j++)
            out[(size_t)(gi*8 + i)*DV + gj + 32*j] = acc[i][j];
}

// ---------------- Scan --------------------------------------------------------
__global__ void scan_k(float* __restrict__ curr_kv, const float* __restrict__ decay)
{
    int bh = blockIdx.x >> 7;
    int e  = ((blockIdx.x & 127) << 8) + threadIdx.x;
    float dC = powf(decay[bh & 7], 128.f);
    size_t base = (size_t)bh * NCHUNK * STATE;
    float s = 0.f;
    #pragma unroll
    for (int c = 0; c < NCHUNK; c++) {
        g_sin[base + (size_t)c*STATE + e] = s;
        s = s*dC + g_kvc[base + (size_t)c*STATE + e];
    }
    curr_kv[(size_t)bh*STATE + e] = s;
}

// ---------------- Pass B ------------------------------------------------------
__global__ __launch_bounds__(512, 1) void pass_b(
    const float* __restrict__ qkv, const float* __restrict__ decay)
{
    extern __shared__ float sm[];
    float* dpow = sm;
    float* As   = sm + 128;
    float* Ta   = As + 128*129;
    float* Tb   = Ta + 2048;

    int blk = blockIdx.x;
    int c = blk & 15, bh = blk >> 4;
    int b = bh >> 3, h = bh & 7;
    int tid = threadIdx.x;
    float dec = decay[h];
    for (int i = tid; i < 128; i += 512) dpow[i] = powf(dec, (float)i);

    int gi = tid >> 5, gj = tid & 31;

    const float* Qb = qkv + ((size_t)(b*TT) + (size_t)c*CHUNK)*QKVC + h*DK;
    const float* Kb = Qb + QKD;
    const float* Vb = qkv + ((size_t)(b*TT) + (size_t)c*CHUNK)*QKVC + 2*QKD + h*DV;

    {
        float acc1[8][4];
        #pragma unroll
        for (int i = 0; i < 8; i++)
            #pragma unroll
            for (int j = 0; j < 4; j++) acc1[i][j] = 0.f;

        for (int k0 = 0; k0 < 128; k0 += 16) {
            for (int u = tid; u < 2048; u += 512) {
                int t = u >> 4, kk = u & 15;
                Ta[kk*128 + t] = Qb[(size_t)t*QKVC + k0 + kk];
                Tb[kk*128 + t] = Kb[(size_t)t*QKVC + k0 + kk];
            }
            __syncthreads();
            #pragma unroll
            for (int kk = 0; kk < 16; kk++) {
                float a[8], bb[4];
                #pragma unroll
                for (int i = 0; i < 8; i++) a[i] = Ta[kk*128 + gi*8 + i];
                #pragma unroll
                for (int j = 0; j < 4; j++) bb[j] = Tb[kk*128 + gj + 32*j];
                #pragma unroll
                for (int i = 0; i < 8; i++)
                    #pragma unroll
                    for (int j = 0; j < 4; j++)
                        acc1[i][j] += a[i] * bb[j];
            }
            __syncthreads();
        }
        #pragma unroll
        for (int i = 0; i < 8; i++) {
            int t = gi*8 + i;
            #pragma unroll
            for (int j = 0; j < 4; j++) {
                int s = gj + 32*j;
                As[t*129 + s] = (t >= s) ? acc1[i][j] * dpow[t - s] : 0.f;
            }
        }
    }
    __syncthreads();

    float acc[8][8];
    #pragma unroll
    for (int i = 0; i < 8; i++)
        #pragma unroll
        for (int j = 0; j < 8; j++) acc[i][j] = 0.f;

    const float* Sc = g_sin + ((size_t)bh*NCHUNK + c)*STATE;
    for (int k0 = 0; k0 < 128; k0 += 16) {
        for (int u = tid; u < 2048; u += 512) {
            int t = u >> 4, kk = u & 15;
            Ta[kk*128 + t] = Qb[(size_t)t*QKVC + k0 + kk];
        }
        for (int u = tid; u < 4096; u += 512) {
            int kk = u >> 8, v = u & 255;
            Tb[kk*256 + v] = Sc[(size_t)(k0 + kk)*DV + v];
        }
        __syncthreads();
        #pragma unroll
        for (int kk = 0; kk < 16; kk++) {
            float a[8], bb[8];
            #pragma unroll
            for (int i = 0; i < 8; i++) a[i] = Ta[kk*128 + gi*8 + i];
            #pragma unroll
            for (int j = 0; j < 8; j++) bb[j] = Tb[kk*256 + gj + 32*j];
            #pragma unroll
            for (int i = 0; i < 8; i++)
                #pragma unroll
                for (int j = 0; j < 8; j++)
                    acc[i][j] += a[i] * bb[j];
        }
        __syncthreads();
    }
    #pragma unroll
    for (int i = 0; i < 8; i++) {
        float f = dpow[gi*8 + i] * dec;
        #pragma unroll
        for (int j = 0; j < 8; j++) acc[i][j] *= f;
    }

    for (int s0 = 0; s0 < 128; s0 += 16) {
        for (int u = tid; u < 4096; u += 512) {
            int ss = u >> 8, v = u & 255;
            Tb[ss*256 + v] = Vb[(size_t)(s0 + ss)*QKVC + v];
        }
        __syncthreads();
        #pragma unroll
        for (int ss = 0; ss < 16; ss++) {
            float a[8], bb[8];
            #pragma unroll
            for (int i = 0; i < 8; i++) a[i] = As[(gi*8 + i)*129 + s0 + ss];
            #pragma unroll
            for (int j = 0; j < 8; j++) bb[j] = Tb[ss*256 + gj + 32*j];
            #pragma unroll
            for (int i = 0; i < 8; i++)
                #pragma unroll
                for (int j = 0; j < 8; j++)
                    acc[i][j] += a[i] * bb[j];
        }
        __syncthreads();
    }

    float* Op = g_O + ((size_t)bh*TT + (size_t)c*CHUNK)*DV;
    #pragma unroll
    for (int i = 0; i < 8; i++)
        #pragma unroll
        for (int j = 0; j < 8; j++)
            Op[(size_t)(gi*8 + i)*DV + gj + 32*j] = acc[i][j];
}

// ---------------- GroupNorm + silu-gate; emits split-bf16 Y -------------------
__global__ void norm_gate(void)
{
    int row = blockIdx.x;
    int b = row >> 11, t = row & (TT - 1);
    int h = threadIdx.x >> 5, lane = threadIdx.x & 31;

    const float* op = g_O + (((size_t)(b*NH + h))*TT + t)*DV;
    float x[8];
    float s = 0.f;
    #pragma unroll
    for (int i = 0; i < 8; i++) { x[i] = op[lane + 32*i]; s += x[i]; }
    #pragma unroll
    for (int o = 16; o > 0; o >>= 1) s += __shfl_xor_sync(0xffffffffu, s, o);
    float mu = s * (1.f/256.f);
    float v = 0.f;
    #pragma unroll
    for (int i = 0; i < 8; i++) { float d = x[i] - mu; v += d*d; }
    #pragma unroll
    for (int o = 16; o > 0; o >>= 1) v += __shfl_xor_sync(0xffffffffu, v, o);
    float r = rsqrtf(v * (1.f/256.f) + 1e-5f);

    const float* gp = g_gate + (size_t)row*VD + h*DV;
    __nv_bfloat16* yh = g_yh + (size_t)row*VD + h*DV;
    __nv_bfloat16* yl = g_yl + (size_t)row*VD + h*DV;
    #pragma unroll
    for (int i = 0; i < 8; i++) {
        float y = gp[lane + 32*i] * (x[i] - mu) * r;
        __nv_bfloat16 hh = __float2bfloat16(y);
        yh[lane + 32*i] = hh;
        yl[lane + 32*i] = __float2bfloat16(y - __bfloat162float(hh));
    }
}

// ---------------- launch -----------------------------------------------------
extern "C" void kernel_launch(void* const* d_in, const int* in_sizes, int n_in,
                              void* d_out, int out_size)
{
    (void)in_sizes; (void)n_in; (void)out_size;
    const float* X     = (const float*)d_in[0];
    const float* Wqkv  = (const float*)d_in[1];
    const float* Wg    = (const float*)d_in[2];
    const float* Wproj = (const float*)d_in[3];
    const float* decay = (const float*)d_in[4];
    float* out = (float*)d_out;
    float* curr_kv = out + (size_t)ROWS * DM;

    float *qkv, *gate;
    __nv_bfloat16 *xh, *xl, *wqh, *wql, *wgh, *wgl, *wph, *wpl, *yh, *yl;
    cudaGetSymbolAddress((void**)&qkv,  g_qkv);
    cudaGetSymbolAddress((void**)&gate, g_gate);
    cudaGetSymbolAddress((void**)&xh,  g_xh);
    cudaGetSymbolAddress((void**)&xl,  g_xl);
    cudaGetSymbolAddress((void**)&wqh, g_wqh);
    cudaGetSymbolAddress((void**)&wql, g_wql);
    cudaGetSymbolAddress((void**)&wgh, g_wgh);
    cudaGetSymbolAddress((void**)&wgl, g_wgl);
    cudaGetSymbolAddress((void**)&wph, g_wph);
    cudaGetSymbolAddress((void**)&wpl, g_wpl);
    cudaGetSymbolAddress((void**)&yh,  g_yh);
    cudaGetSymbolAddress((void**)&yl,  g_yl);

    const int smemB = (128 + 128*129 + 2048 + 4096) * 4;
    cudaFuncSetAttribute(pass_b, cudaFuncAttributeMaxDynamicSharedMemorySize, smemB);
    cudaFuncSetAttribute(gemm_mma, cudaFuncAttributeMaxDynamicSharedMemorySize, SMEM_GEMM);

    // 0) split/transpose operands to bf16 hi/lo
    {
        size_t n4 = (size_t)ROWS * DM / 4;
        split_kernel<<<(unsigned)((n4 + 255)/256), 256>>>((const float4*)X, xh, xl, n4);
    }
    tsplit_kernel<<<dim3(QKVC/32, DM/32), dim3(32,8)>>>(Wqkv,  wqh, wql, DM, QKVC);
    tsplit_kernel<<<dim3(VD/32,   DM/32), dim3(32,8)>>>(Wg,    wgh, wgl, DM, VD);
    tsplit_kernel<<<dim3(DM/32,   VD/32), dim3(32,8)>>>(Wproj, wph, wpl, VD, DM);

    // 1) QKV = X @ W_qkv
    gemm_mma<<<dim3(QKVC/BN, ROWS/BM), 256, SMEM_GEMM>>>(xh, xl, wqh, wql, qkv, ROWS, QKVC, DM, 0);
    // 2) gate = silu(X @ W_g)
    gemm_mma<<<dim3(VD/BN, ROWS/BM), 256, SMEM_GEMM>>>(xh, xl, wgh, wgl, gate, ROWS, VD, DM, 1);
    // 3) rotary
    rotary_kernel<<<dim3(ROWS, 2), 256>>>(qkv);
    // 4) per-chunk KV contributions
    pass_a<<<32*NCHUNK, 512>>>(qkv, decay);
    // 5) state scan -> S_in + curr_kv
    scan_k<<<32*128, 256>>>(curr_kv, decay);
    // 6) retention output
    pass_b<<<32*NCHUNK, 512, smemB>>>(qkv, decay);
    // 7) groupnorm + gate -> split-bf16 Y
    norm_gate<<<ROWS, 256>>>();
    // 8) proj_out = Y @ W_proj
    gemm_mma<<<dim3(DM/BN, ROWS/BM), 256, SMEM_GEMM>>>(yh, yl, wph, wpl, out, ROWS, DM, VD, 0);
}

// round 4
// speedup vs baseline: 2.4063x; 1.2342x over previous
#include <cuda_runtime.h>
#include <cuda_bf16.h>
#include <math.h>
#include <stdint.h>

// Problem constants
#define BB     4
#define TT     2048
#define DM     1024
#define QKD    1024
#define VD     2048
#define NH     8
#define DK     128
#define DV     256
#define CHUNK  128
#define NCHUNK 16
#define ROWS   (BB*TT)       // 8192
#define QKVC   (2*QKD + VD)  // 4096
#define STATE  (DK*DV)       // 32768

// ---------------- scratch (global __device__ arrays; no allocation) ----------
__device__ float g_qkv [ (size_t)ROWS * QKVC ];
__device__ float g_gate[ (size_t)ROWS * VD   ];
__device__ float g_kvc [ (size_t)32 * NCHUNK * STATE ];   // [bh][c][dv][dk]
__device__ float g_O   [ (size_t)32 * TT * DV ];

// split-bf16 operand buffers (GEMMs)
__device__ __nv_bfloat16 g_xh [ (size_t)ROWS * DM ];
__device__ __nv_bfloat16 g_xl [ (size_t)ROWS * DM ];
__device__ __nv_bfloat16 g_wqh[ (size_t)QKVC * DM ];
__device__ __nv_bfloat16 g_wql[ (size_t)QKVC * DM ];
__device__ __nv_bfloat16 g_wgh[ (size_t)VD * DM ];
__device__ __nv_bfloat16 g_wgl[ (size_t)VD * DM ];
__device__ __nv_bfloat16 g_wph[ (size_t)DM * VD ];
__device__ __nv_bfloat16 g_wpl[ (size_t)DM * VD ];
__device__ __nv_bfloat16 g_yh [ (size_t)ROWS * VD ];
__device__ __nv_bfloat16 g_yl [ (size_t)ROWS * VD ];

// retention split-bf16 buffers (q~ = q*rs*dec^tau, k~ = k*dec^-tau), natural layout
__device__ __nv_bfloat16 g_qth[ (size_t)ROWS * QKD ];
__device__ __nv_bfloat16 g_qtl[ (size_t)ROWS * QKD ];
__device__ __nv_bfloat16 g_kth[ (size_t)ROWS * QKD ];
__device__ __nv_bfloat16 g_ktl[ (size_t)ROWS * QKD ];
__device__ __nv_bfloat16 g_vsh[ (size_t)ROWS * VD ];
__device__ __nv_bfloat16 g_vsl[ (size_t)ROWS * VD ];
__device__ __nv_bfloat16 g_sh [ (size_t)32 * NCHUNK * STATE ];  // S_in^T [dv][dk] hi
__device__ __nv_bfloat16 g_sl [ (size_t)32 * NCHUNK * STATE ];  // lo

// ======================= helpers =============================================
__device__ __forceinline__ uint32_t smem_u32(const void* p) {
    uint32_t a;
    asm("{ .reg .u64 t; cvta.to.shared.u64 t, %1; cvt.u32.u64 %0, t; }"
        : "=r"(a) : "l"(p));
    return a;
}
__device__ __forceinline__ void cpa16(uint32_t s, const void* g) {
    asm volatile("cp.async.cg.shared.global [%0], [%1], 16;" :: "r"(s), "l"(g));
}
#define CP_COMMIT() asm volatile("cp.async.commit_group;" ::: "memory")
#define CP_WAIT0()  asm volatile("cp.async.wait_group 0;" ::: "memory")

__device__ __forceinline__ void ldm_x4(uint32_t* r, uint32_t addr) {
    asm volatile("ldmatrix.sync.aligned.m8n8.x4.shared.b16 {%0,%1,%2,%3}, [%4];"
        : "=r"(r[0]), "=r"(r[1]), "=r"(r[2]), "=r"(r[3]) : "r"(addr));
}
__device__ __forceinline__ void ldm_x4t(uint32_t* r, uint32_t addr) {
    asm volatile("ldmatrix.sync.aligned.m8n8.x4.trans.shared.b16 {%0,%1,%2,%3}, [%4];"
        : "=r"(r[0]), "=r"(r[1]), "=r"(r[2]), "=r"(r[3]) : "r"(addr));
}
__device__ __forceinline__ void mma_bf16(float* c, const uint32_t* a,
                                         uint32_t b0, uint32_t b1) {
    asm volatile(
        "mma.sync.aligned.m16n8k16.row.col.f32.bf16.bf16.f32 "
        "{%0,%1,%2,%3}, {%4,%5,%6,%7}, {%8,%9}, {%0,%1,%2,%3};"
        : "+f"(c[0]), "+f"(c[1]), "+f"(c[2]), "+f"(c[3])
        : "r"(a[0]), "r"(a[1]), "r"(a[2]), "r"(a[3]), "r"(b0), "r"(b1));
}

// ======================= split / transpose-split kernels =====================
__global__ void split_kernel(const float4* __restrict__ in,
                             __nv_bfloat16* __restrict__ oh,
                             __nv_bfloat16* __restrict__ ol, size_t n4)
{
    size_t i = (size_t)blockIdx.x * blockDim.x + threadIdx.x;
    if (i >= n4) return;
    float4 v = in[i];
    __nv_bfloat16 h0 = __float2bfloat16(v.x), h1 = __float2bfloat16(v.y);
    __nv_bfloat16 h2 = __float2bfloat16(v.z), h3 = __float2bfloat16(v.w);
    __nv_bfloat162* oh2 = (__nv_bfloat162*)(oh + i*4);
    __nv_bfloat162* ol2 = (__nv_bfloat162*)(ol + i*4);
    oh2[0] = __nv_bfloat162(h0, h1);
    oh2[1] = __nv_bfloat162(h2, h3);
    ol2[0] = __nv_bfloat162(__float2bfloat16(v.x - __bfloat162float(h0)),
                            __float2bfloat16(v.y - __bfloat162float(h1)));
    ol2[1] = __nv_bfloat162(__float2bfloat16(v.z - __bfloat162float(h2)),
                            __float2bfloat16(v.w - __bfloat162float(h3)));
}

// in [K,N] fp32 -> out [N,K] bf16 hi/lo
__global__ void tsplit_kernel(const float* __restrict__ in,
                              __nv_bfloat16* __restrict__ oh,
                              __nv_bfloat16* __restrict__ ol, int K, int N)
{
    __shared__ float s[32][33];
    int k0 = blockIdx.y * 32, n0 = blockIdx.x * 32;
    for (int i = threadIdx.y; i < 32; i += 8)
        s[i][threadIdx.x] = in[(size_t)(k0 + i) * N + n0 + threadIdx.x];
    __syncthreads();
    for (int i = threadIdx.y; i < 32; i += 8) {
        float v = s[threadIdx.x][i];
        __nv_bfloat16 h = __float2bfloat16(v);
        size_t o = (size_t)(n0 + i) * K + k0 + threadIdx.x;
        oh[o] = h;
        ol[o] = __float2bfloat16(v - __bfloat162float(h));
    }
}

// ======================= mma.sync split-bf16 GEMM ============================
#define BM   128
#define BN   128
#define BKC  32
#define STRD 40
#define TSZ  (128*STRD)
#define STAGE_E (4*TSZ)
#define SMEM_GEMM (2*STAGE_E*2)

__global__ __launch_bounds__(256) void gemm_mma(
    const __nv_bfloat16* __restrict__ Ah, const __nv_bfloat16* __restrict__ Al,
    const __nv_bfloat16* __restrict__ Bh, const __nv_bfloat16* __restrict__ Bl,
    float* __restrict__ C, int M, int N, int K, int do_silu)
{
    extern __shared__ char smem[];
    uint32_t sbase = smem_u32(smem);
    int tid = threadIdx.x, wid = tid >> 5, lane = tid & 31;
    int m0 = blockIdx.y * BM, n0 = blockIdx.x * BN;
    int wm = wid >> 2, wn = wid & 3;

    float acc[4][4][4];
    #pragma unroll
    for (int i = 0; i < 4; i++)
        #pragma unroll
        for (int j = 0; j < 4; j++)
            #pragma unroll
            for (int q = 0; q < 4; q++) acc[i][j][q] = 0.f;

    const int nch = K / BKC;
    const __nv_bfloat16* srcs[4] = {Ah, Al, Bh, Bl};

    auto load_stage = [&](int c, int st) {
        size_t kb = (size_t)c * BKC;
        uint32_t so = sbase + (uint32_t)st * STAGE_E * 2;
        #pragma unroll
        for (int q = 0; q < 4; q++) {
            int base_row = (q < 2) ? m0 : n0;
            const __nv_bfloat16* src = srcs[q];
            #pragma unroll
            for (int it = 0; it < 2; it++) {
                int u = tid + it * 256;
                int r = u >> 2, sg = u & 3;
                cpa16(so + (uint32_t)q * TSZ * 2 + r * (STRD*2) + sg * 16,
                      src + (size_t)(base_row + r) * K + kb + sg * 8);
            }
        }
        CP_COMMIT();
    };

    load_stage(0, 0);

    for (int c = 0; c < nch; c++) {
        int st = c & 1;
        if (c + 1 < nch) {
            load_stage(c + 1, st ^ 1);
            asm volatile("cp.async.wait_group 1;" ::: "memory");
        } else {
            asm volatile("cp.async.wait_group 0;" ::: "memory");
        }
        __syncthreads();

        uint32_t so = sbase + (uint32_t)st * STAGE_E * 2;
        uint32_t aoff_h = so;
        uint32_t aoff_l = so + TSZ * 2;
        uint32_t boff_h = so + 2 * TSZ * 2;
        uint32_t boff_l = so + 3 * TSZ * 2;

        int arow = wm * 64 + (lane & 15);
        int brow = wn * 32 + (lane & 15);
        int colb = (lane >> 4) * 16;

        #pragma unroll
        for (int kf = 0; kf < 2; kf++) {
            uint32_t ah[4][4], al[4][4];
            #pragma unroll
            for (int mf = 0; mf < 4; mf++) {
                uint32_t ao = (uint32_t)(arow + mf * 16) * (STRD*2) + kf * 32 + colb;
                ldm_x4(ah[mf], aoff_h + ao);
                ldm_x4(al[mf], aoff_l + ao);
            }
            uint32_t bh[4][2], bl[4][2];
            #pragma unroll
            for (int pp = 0; pp < 2; pp++) {
                uint32_t bo = (uint32_t)(brow + pp * 16) * (STRD*2) + kf * 32 + colb;
                uint32_t r[4];
                ldm_x4(r, boff_h + bo);
                bh[pp*2][0] = r[0]; bh[pp*2][1] = r[2];
                bh[pp*2+1][0] = r[1]; bh[pp*2+1][1] = r[3];
                ldm_x4(r, boff_l + bo);
                bl[pp*2][0] = r[0]; bl[pp*2][1] = r[2];
                bl[pp*2+1][0] = r[1]; bl[pp*2+1][1] = r[3];
            }
            #pragma unroll
            for (int mf = 0; mf < 4; mf++)
                #pragma unroll
                for (int nf = 0; nf < 4; nf++) {
                    mma_bf16(acc[mf][nf], ah[mf], bh[nf][0], bh[nf][1]);
                    mma_bf16(acc[mf][nf], ah[mf], bl[nf][0], bl[nf][1]);
                    mma_bf16(acc[mf][nf], al[mf], bh[nf][0], bh[nf][1]);
                }
        }
        __syncthreads();
    }

    #pragma unroll
    for (int mf = 0; mf < 4; mf++) {
        int row = m0 + wm * 64 + mf * 16 + (lane >> 2);
        #pragma unroll
        for (int nf = 0; nf < 4; nf++) {
            int col = n0 + wn * 32 + nf * 8 + (lane & 3) * 2;
            float v0 = acc[mf][nf][0], v1 = acc[mf][nf][1];
            float v2 = acc[mf][nf][2], v3 = acc[mf][nf][3];
            if (do_silu) {
                v0 = v0 / (1.f + expf(-v0)); v1 = v1 / (1.f + expf(-v1));
                v2 = v2 / (1.f + expf(-v2)); v3 = v3 / (1.f + expf(-v3));
            }
            *(float2*)(C + (size_t)row * N + col)       = make_float2(v0, v1);
            *(float2*)(C + (size_t)(row + 8) * N + col) = make_float2(v2, v3);
        }
    }
}

// ---------------- rotary + decay-fold + split -------------------------------
// q~ = rot(q)*rs*dec^tau, k~ = rot(k)*dec^-tau; hi/lo bf16, natural layout
__global__ void rotary_split(const float* __restrict__ qkv,
                             __nv_bfloat16* __restrict__ qh_, __nv_bfloat16* __restrict__ ql_,
                             __nv_bfloat16* __restrict__ kh_, __nv_bfloat16* __restrict__ kl_,
                             const float* __restrict__ decay)
{
    int row = blockIdx.x;
    int t   = row & (TT - 1);
    int tau = t & (CHUNK - 1);
    int j   = blockIdx.y * 256 + threadIdx.x;   // 0..511
    if (j >= 512) return;

    float base = (2.f*(float)j + 0.4f*1024.f) * (1.f/(1.4f*1024.f));
    float sc = expf(((float)t * (1.f/512.f)) * logf(base));
    float inv_freq = expf(-(float)j * (1.f/512.f) * logf(10000.f));
    float ang = (float)t * inv_freq;
    float sn, cs;
    sincosf(ang, &sn, &cs);

    int h = j >> 6;
    float dec = decay[h];
    const float rs = 0.08838834764831845f;
    float wq = powf(dec, (float)tau) * rs;
    float wk = powf(dec, -(float)tau);

    const float* p = qkv + (size_t)row * QKVC;
    float qe = p[2*j], qo = p[2*j+1];
    float cq = cs*sc, sq = sn*sc;
    float q0 = (qe*cq - qo*sq) * wq;
    float q1 = (qo*cq + qe*sq) * wq;

    float ke = p[QKD + 2*j], ko = p[QKD + 2*j+1];
    float ci = cs/sc, si = sn/sc;
    float k0 = (ke*ci - ko*si) * wk;
    float k1 = (ko*ci + ke*si) * wk;

    __nv_bfloat16 q0h = __float2bfloat16(q0), q1h = __float2bfloat16(q1);
    __nv_bfloat16 k0h = __float2bfloat16(k0), k1h = __float2bfloat16(k1);
    size_t o = (size_t)row * QKD + 2*j;
    *(__nv_bfloat162*)(qh_ + o) = __nv_bfloat162(q0h, q1h);
    *(__nv_bfloat162*)(ql_ + o) = __nv_bfloat162(
        __float2bfloat16(q0 - __bfloat162float(q0h)),
        __float2bfloat16(q1 - __bfloat162float(q1h)));
    *(__nv_bfloat162*)(kh_ + o) = __nv_bfloat162(k0h, k1h);
    *(__nv_bfloat162*)(kl_ + o) = __nv_bfloat162(
        __float2bfloat16(k0 - __bfloat162float(k0h)),
        __float2bfloat16(k1 - __bfloat162float(k1h)));
}

// split v part of qkv -> vh/vl [row][2048]
__global__ void v_split(const float* __restrict__ qkv,
                        __nv_bfloat16* __restrict__ vh_, __nv_bfloat16* __restrict__ vl_)
{
    int row = blockIdx.x;
    int i = blockIdx.y * 256 + threadIdx.x;      // 0..511 float4
    float4 v = *(const float4*)(qkv + (size_t)row * QKVC + 2*QKD + i*4);
    __nv_bfloat16 h0 = __float2bfloat16(v.x), h1 = __float2bfloat16(v.y);
    __nv_bfloat16 h2 = __float2bfloat16(v.z), h3 = __float2bfloat16(v.w);
    size_t o = (size_t)row * VD + i*4;
    *(__nv_bfloat162*)(vh_ + o)     = __nv_bfloat162(h0, h1);
    *(__nv_bfloat162*)(vh_ + o + 2) = __nv_bfloat162(h2, h3);
    *(__nv_bfloat162*)(vl_ + o)     = __nv_bfloat162(
        __float2bfloat16(v.x - __bfloat162float(h0)),
        __float2bfloat16(v.y - __bfloat162float(h1)));
    *(__nv_bfloat162*)(vl_ + o + 2) = __nv_bfloat162(
        __float2bfloat16(v.z - __bfloat162float(h2)),
        __float2bfloat16(v.w - __bfloat162float(h3)));
}

// ======================= Pass A (mma): KV_c^T[dv][dk] ========================
// C[dv][dk] = dec^127 * sum_tau V[tau][dv] * K~[tau][dk]; A=V^T (trans), B=K~^T (trans)
#define PA_VH 0
#define PA_VL (128*264)
#define PA_KH (2*128*264)
#define PA_KL (2*128*264 + 128*136)
#define PA_SMEM ((2*128*264 + 2*128*136) * 2)

__global__ __launch_bounds__(256, 1) void pass_a_mma(
    const __nv_bfloat16* __restrict__ kh_, const __nv_bfloat16* __restrict__ kl_,
    const __nv_bfloat16* __restrict__ vh_, const __nv_bfloat16* __restrict__ vl_,
    const float* __restrict__ decay)
{
    extern __shared__ char smem[];
    uint32_t sb = smem_u32(smem);
    int tid = threadIdx.x, wid = tid >> 5, lane = tid & 31;
    int c = blockIdx.x & 15, bh = blockIdx.x >> 4;
    int b = bh >> 3, h = bh & 7;
    float s127 = powf(decay[h], 127.f);
    size_t g = (size_t)b*TT + (size_t)c*CHUNK;

    // load V [128][256] (stride 264) and K~ [128][128] (stride 136), hi/lo
    #pragma unroll
    for (int it = 0; it < 16; it++) {       // V: 4096 segs per buffer
        int u = tid + it * 256;
        int r = u >> 5, sg = u & 31;
        uint32_t so = (uint32_t)(r*264 + sg*8) * 2;
        const __nv_bfloat16* sh = vh_ + (g + r)*VD + h*DV + sg*8;
        const __nv_bfloat16* sl = vl_ + (g + r)*VD + h*DV + sg*8;
        cpa16(sb + PA_VH*2 + so, sh);
        cpa16(sb + PA_VL*2 + so, sl);
    }
    #pragma unroll
    for (int it = 0; it < 8; it++) {        // K: 2048 segs per buffer
        int u = tid + it * 256;
        int r = u >> 4, sg = u & 15;
        uint32_t so = (uint32_t)(r*136 + sg*8) * 2;
        cpa16(sb + PA_KH*2 + so, kh_ + (g + r)*QKD + h*DK + sg*8);
        cpa16(sb + PA_KL*2 + so, kl_ + (g + r)*QKD + h*DK + sg*8);
    }
    CP_COMMIT(); CP_WAIT0();
    __syncthreads();

    int wm = wid >> 1, wn = wid & 1;        // 4m x 2n; m tile 64 (dv), n tile 64 (dk)
    float acc[4][8][4];
    #pragma unroll
    for (int i = 0; i < 4; i++)
        #pragma unroll
        for (int j = 0; j < 8; j++)
            #pragma unroll
            for (int q = 0; q < 4; q++) acc[i][j][q] = 0.f;

    int krow = (lane & 7) + ((lane >> 4) & 1) * 8;
    int cadd = ((lane >> 3) & 1) * 8;

    for (int ks = 0; ks < 8; ks++) {
        int kr = ks*16 + krow;
        uint32_t avh[4][4], avl[4][4];
        #pragma unroll
        for (int mf = 0; mf < 4; mf++) {
            uint32_t ao = (uint32_t)(kr*264 + wm*64 + mf*16 + cadd) * 2;
            ldm_x4t(avh[mf], sb + PA_VH*2 + ao);
            ldm_x4t(avl[mf], sb + PA_VL*2 + ao);
        }
        uint32_t bkh[8][2], bkl[8][2];
        #pragma unroll
        for (int pp = 0; pp < 4; pp++) {
            uint32_t bo = (uint32_t)(kr*136 + wn*64 + pp*16 + cadd) * 2;
            uint32_t r[4];
            ldm_x4t(r, sb + PA_KH*2 + bo);
            bkh[pp*2][0] = r[0]; bkh[pp*2][1] = r[2];
            bkh[pp*2+1][0] = r[1]; bkh[pp*2+1][1] = r[3];
            ldm_x4t(r, sb + PA_KL*2 + bo);
            bkl[pp*2][0] = r[0]; bkl[pp*2][1] = r[2];
            bkl[pp*2+1][0] = r[1]; bkl[pp*2+1][1] = r[3];
        }
        #pragma unroll
        for (int mf = 0; mf < 4; mf++)
            #pragma unroll
            for (int nf = 0; nf < 8; nf++) {
                mma_bf16(acc[mf][nf], avh[mf], bkh[nf][0], bkh[nf][1]);
                mma_bf16(acc[mf][nf], avh[mf], bkl[nf][0], bkl[nf][1]);
                mma_bf16(acc[mf][nf], avl[mf], bkh[nf][0], bkh[nf][1]);
            }
    }

    float* out = g_kvc + ((size_t)bh*NCHUNK + c)*STATE;
    #pragma unroll
    for (int mf = 0; mf < 4; mf++) {
        int dv = wm*64 + mf*16 + (lane >> 2);
        #pragma unroll
        for (int nf = 0; nf < 8; nf++) {
            int dk = wn*64 + nf*8 + (lane & 3)*2;
            *(float2*)(out + (size_t)dv*DK + dk) =
                make_float2(acc[mf][nf][0]*s127, acc[mf][nf][1]*s127);
            *(float2*)(out + (size_t)(dv+8)*DK + dk) =
                make_float2(acc[mf][nf][2]*s127, acc[mf][nf][3]*s127);
        }
    }
}

// ---------------- Scan: S_in^T hi/lo + curr_kv -------------------------------
__global__ void scan_k(float* __restrict__ curr_kv, const float* __restrict__ decay)
{
    int bh = blockIdx.x >> 7;
    int e  = ((blockIdx.x & 127) << 8) + threadIdx.x;   // e = dv*128+dk
    float dC = powf(decay[bh & 7], 128.f);
    size_t base = (size_t)bh * NCHUNK * STATE;
    float s = 0.f;
    #pragma unroll
    for (int c = 0; c < NCHUNK; c++) {
        __nv_bfloat16 hh = __float2bfloat16(s);
        g_sh[base + (size_t)c*STATE + e] = hh;
        g_sl[base + (size_t)c*STATE + e] = __float2bfloat16(s - __bfloat162float(hh));
        s = s*dC + g_kvc[base + (size_t)c*STATE + e];
    }
    int dv = e >> 7, dk = e & 127;
    curr_kv[(size_t)bh*STATE + (size_t)dk*DV + dv] = s;
}

// ======================= Pass B (mma) ========================================
// stage1: A[t][s] = tri(Q~ K~^T); stage2: O = dec*(Q~ S_in) + A V
#define PB_QH  0
#define PB_QL  (128*136)
#define PB_R2H (2*128*136)          // K~ then As
#define PB_R2L (3*128*136)
#define PB_R3H (4*128*136)          // S chunks [256][72] / V chunks [64][264]
#define PB_R3L (4*128*136 + 256*72)
#define PB_SMEM ((4*128*136 + 2*256*72) * 2)

__global__ __launch_bounds__(256, 1) void pass_b_mma(
    const __nv_bfloat16* __restrict__ qh_, const __nv_bfloat16* __restrict__ ql_,
    const __nv_bfloat16* __restrict__ kh_, const __nv_bfloat16* __restrict__ kl_,
    const __nv_bfloat16* __restrict__ vh_, const __nv_bfloat16* __restrict__ vl_,
    const float* __restrict__ decay)
{
    extern __shared__ char smem[];
    uint32_t sb = smem_u32(smem);
    int tid = threadIdx.x, wid = tid >> 5, lane = tid & 31;
    int c = blockIdx.x & 15, bh = blockIdx.x >> 4;
    int b = bh >> 3, h = bh & 7;
    float dec = decay[h];
    size_t g = (size_t)b*TT + (size_t)c*CHUNK;

    // ---- load Q~ and K~ tiles [128][128] stride 136, hi/lo ----
    #pragma unroll
    for (int it = 0; it < 8; it++) {
        int u = tid + it * 256;
        int r = u >> 4, sg = u & 15;
        uint32_t so = (uint32_t)(r*136 + sg*8) * 2;
        cpa16(sb + PB_QH*2 + so,  qh_ + (g + r)*QKD + h*DK + sg*8);
        cpa16(sb + PB_QL*2 + so,  ql_ + (g + r)*QKD + h*DK + sg*8);
        cpa16(sb + PB_R2H*2 + so, kh_ + (g + r)*QKD + h*DK + sg*8);
        cpa16(sb + PB_R2L*2 + so, kl_ + (g + r)*QKD + h*DK + sg*8);
    }
    CP_COMMIT(); CP_WAIT0();
    __syncthreads();

    int wm = wid >> 2, wn = wid & 3;
    int arow = wm*64 + (lane & 15);
    int colb = (lane >> 4) * 8;

    // ---- stage 1: acc1 = Q~ K~^T (warp tile 64x32) ----
    float acc1[4][4][4];
    #pragma unroll
    for (int i = 0; i < 4; i++)
        #pragma unroll
        for (int j = 0; j < 4; j++)
            #pragma unroll
            for (int q = 0; q < 4; q++) acc1[i][j][q] = 0.f;

    for (int ks = 0; ks < 8; ks++) {
        uint32_t ah[4][4], al[4][4];
        #pragma unroll
        for (int mf = 0; mf < 4; mf++) {
            uint32_t ao = (uint32_t)((arow + mf*16)*136 + ks*16 + colb) * 2;
            ldm_x4(ah[mf], sb + PB_QH*2 + ao);
            ldm_x4(al[mf], sb + PB_QL*2 + ao);
        }
        uint32_t bkh[4][2], bkl[4][2];
        #pragma unroll
        for (int pp = 0; pp < 2; pp++) {
            uint32_t bo = (uint32_t)((wn*32 + pp*16 + (lane & 15))*136 + ks*16 + colb) * 2;
            uint32_t r[4];
            ldm_x4(r, sb + PB_R2H*2 + bo);
            bkh[pp*2][0] = r[0]; bkh[pp*2][1] = r[2];
            bkh[pp*2+1][0] = r[1]; bkh[pp*2+1][1] = r[3];
            ldm_x4(r, sb + PB_R2L*2 + bo);
            bkl[pp*2][0] = r[0]; bkl[pp*2][1] = r[2];
            bkl[pp*2+1][0] = r[1]; bkl[pp*2+1][1] = r[3];
        }
        #pragma unroll
        for (int mf = 0; mf < 4; mf++)
            #pragma unroll
            for (int nf = 0; nf < 4; nf++) {
                mma_bf16(acc1[mf][nf], ah[mf], bkh[nf][0], bkh[nf][1]);
                mma_bf16(acc1[mf][nf], ah[mf], bkl[nf][0], bkl[nf][1]);
                mma_bf16(acc1[mf][nf], al[mf], bkh[nf][0], bkh[nf][1]);
            }
    }
    __syncthreads();   // all K~ reads done; region2 becomes As

    // ---- causal mask + hi/lo split -> As in region2 ----
    #pragma unroll
    for (int mf = 0; mf < 4; mf++) {
        #pragma unroll
        for (int nf = 0; nf < 4; nf++) {
            #pragma unroll
            for (int half = 0; half < 2; half++) {
                int t = wm*64 + mf*16 + (lane >> 2) + half*8;
                int s0 = wn*32 + nf*8 + (lane & 3)*2;
                float v0 = (t >= s0)     ? acc1[mf][nf][half*2]   : 0.f;
                float v1 = (t >= s0 + 1) ? acc1[mf][nf][half*2+1] : 0.f;
                __nv_bfloat16 h0 = __float2bfloat16(v0), h1 = __float2bfloat16(v1);
                __nv_bfloat16* ph = (__nv_bfloat16*)smem + PB_R2H + t*136 + s0;
                __nv_bfloat16* pl = (__nv_bfloat16*)smem + PB_R2L + t*136 + s0;
                *(__nv_bfloat162*)ph = __nv_bfloat162(h0, h1);
                *(__nv_bfloat162*)pl = __nv_bfloat162(
                    __float2bfloat16(v0 - __bfloat162float(h0)),
                    __float2bfloat16(v1 - __bfloat162float(h1)));
            }
        }
    }

    // ---- stage 2: acc = dec*(Q~ @ S^T') + As @ V ; warp tile 64x64 over N=256
    float acc[4][8][4];
    #pragma unroll
    for (int i = 0; i < 4; i++)
        #pragma unroll
        for (int j = 0; j < 8; j++)
            #pragma unroll
            for (int q = 0; q < 4; q++) acc[i][j][q] = 0.f;

    const __nv_bfloat16* ssh = g_sh + ((size_t)bh*NCHUNK + c)*STATE;
    const __nv_bfloat16* ssl = g_sl + ((size_t)bh*NCHUNK + c)*STATE;

    // stage 2a: B = S^T [256 dv][128 dk], k-chunks of 64 (tile stride 72)
    for (int kc = 0; kc < 2; kc++) {
        __syncthreads();
        #pragma unroll
        for (int it = 0; it < 8; it++) {    // 2048 segs per buffer
            int u = tid + it * 256;
            int r = u >> 3, sg = u & 7;
            uint32_t so = (uint32_t)(r*72 + sg*8) * 2;
            cpa16(sb + PB_R3H*2 + so, ssh + (size_t)r*DK + kc*64 + sg*8);
            cpa16(sb + PB_R3L*2 + so, ssl + (size_t)r*DK + kc*64 + sg*8);
        }
        CP_COMMIT(); CP_WAIT0();
        __syncthreads();

        for (int ks = 0; ks < 4; ks++) {
            uint32_t ah[4][4], al[4][4];
            #pragma unroll
            for (int mf = 0; mf < 4; mf++) {
                uint32_t ao = (uint32_t)((arow + mf*16)*136 + kc*64 + ks*16 + colb) * 2;
                ldm_x4(ah[mf], sb + PB_QH*2 + ao);
                ldm_x4(al[mf], sb + PB_QL*2 + ao);
            }
            uint32_t bsh[8][2], bsl[8][2];
            #pragma unroll
            for (int pp = 0; pp < 4; pp++) {
                uint32_t bo = (uint32_t)((wn*64 + pp*16 + (lane & 15))*72 + ks*16 + colb) * 2;
                uint32_t r[4];
                ldm_x4(r, sb + PB_R3H*2 + bo);
                bsh[pp*2][0] = r[0]; bsh[pp*2][1] = r[2];
                bsh[pp*2+1][0] = r[1]; bsh[pp*2+1][1] = r[3];
                ldm_x4(r, sb + PB_R3L*2 + bo);
                bsl[pp*2][0] = r[0]; bsl[pp*2][1] = r[2];
                bsl[pp*2+1][0] = r[1]; bsl[pp*2+1][1] = r[3];
            }
            #pragma unroll
            for (int mf = 0; mf < 4; mf++)
                #pragma unroll
                for (int nf = 0; nf < 8; nf++) {
                    mma_bf16(acc[mf][nf], ah[mf], bsh[nf][0], bsh[nf][1]);
                    mma_bf16(acc[mf][nf], ah[mf], bsl[nf][0], bsl[nf][1]);
                    mma_bf16(acc[mf][nf], al[mf], bsh[nf][0], bsh[nf][1]);
                }
        }
    }
    // scale cross-term by dec (dec^{tau+1} = dec * dec^tau already in q~)
    #pragma unroll
    for (int i = 0; i < 4; i++)
        #pragma unroll
        for (int j = 0; j < 8; j++)
            #pragma unroll
            for (int q = 0; q < 4; q++) acc[i][j][q] *= dec;

    // stage 2b: acc += As @ V; B = V^T via trans from [s][dv], k-chunks of 64
    int krow = (lane & 7) + ((lane >> 4) & 1) * 8;
    int cadd = ((lane >> 3) & 1) * 8;
    for (int kc = 0; kc < 2; kc++) {
        __syncthreads();
        #pragma unroll
        for (int it = 0; it < 8; it++) {    // V chunk [64][256] stride 264: 2048 segs
            int u = tid + it * 256;
            int r = u >> 5, sg = u & 31;
            uint32_t so = (uint32_t)(r*264 + sg*8) * 2;
            cpa16(sb + PB_R3H*2 + so, vh_ + (g + kc*64 + r)*VD + h*DV + sg*8);
            cpa16(sb + PB_R3L*2 + so, vl_ + (g + kc*64 + r)*VD + h*DV + sg*8);
        }
        CP_COMMIT(); CP_WAIT0();
        __syncthreads();

        for (int ks = 0; ks < 4; ks++) {
            uint32_t ah[4][4], al[4][4];
            #pragma unroll
            for (int mf = 0; mf < 4; mf++) {
                uint32_t ao = (uint32_t)((arow + mf*16)*136 + kc*64 + ks*16 + colb) * 2;
                ldm_x4(ah[mf], sb + PB_R2H*2 + ao);
                ldm_x4(al[mf], sb + PB_R2L*2 + ao);
            }
            uint32_t bvh[8][2], bvl[8][2];
            #pragma unroll
            for (int pp = 0; pp < 4; pp++) {
                uint32_t bo = (uint32_t)((ks*16 + krow)*264 + wn*64 + pp*16 + cadd) * 2;
                uint32_t r[4];
                ldm_x4t(r, sb + PB_R3H*2 + bo);
                bvh[pp*2][0] = r[0]; bvh[pp*2][1] = r[2];
                bvh[pp*2+1][0] = r[1]; bvh[pp*2+1][1] = r[3];
                ldm_x4t(r, sb + PB_R3L*2 + bo);
                bvl[pp*2][0] = r[0]; bvl[pp*2][1] = r[2];
                bvl[pp*2+1][0] = r[1]; bvl[pp*2+1][1] = r[3];
            }
            #pragma unroll
            for (int mf = 0; mf < 4; mf++)
                #pragma unroll
                for (int nf = 0; nf < 8; nf++) {
                    mma_bf16(acc[mf][nf], ah[mf], bvh[nf][0], bvh[nf][1]);
                    mma_bf16(acc[mf][nf], ah[mf], bvl[nf][0], bvl[nf][1]);
                    mma_bf16(acc[mf][nf], al[mf], bvh[nf][0], bvh[nf][1]);
                }
        }
    }

    // ---- store O [bh][t][dv] fp32 ----
    float* Op = g_O + ((size_t)bh*TT + (size_t)c*CHUNK)*DV;
    #pragma unroll
    for (int mf = 0; mf < 4; mf++) {
        int t = wm*64 + mf*16 + (lane >> 2);
        #pragma unroll
        for (int nf = 0; nf < 8; nf++) {
            int dv = wn*64 + nf*8 + (lane & 3)*2;
            *(float2*)(Op + (size_t)t*DV + dv) =
                make_float2(acc[mf][nf][0], acc[mf][nf][1]);
            *(float2*)(Op + (size_t)(t+8)*DV + dv) =
                make_float2(acc[mf][nf][2], acc[mf][nf][3]);
        }
    }
}

// ---------------- GroupNorm + silu-gate; emits split-bf16 Y -------------------
__global__ void norm_gate(void)
{
    int row = blockIdx.x;
    int b = row >> 11, t = row & (TT - 1);
    int h = threadIdx.x >> 5, lane = threadIdx.x & 31;

    const float* op = g_O + (((size_t)(b*NH + h))*TT + t)*DV;
    float x[8];
    float s = 0.f;
    #pragma unroll
    for (int i = 0; i < 8; i++) { x[i] = op[lane + 32*i]; s += x[i]; }
    #pragma unroll
    for (int o = 16; o > 0; o >>= 1) s += __shfl_xor_sync(0xffffffffu, s, o);
    float mu = s * (1.f/256.f);
    float v = 0.f;
    #pragma unroll
    for (int i = 0; i < 8; i++) { float d = x[i] - mu; v += d*d; }
    #pragma unroll
    for (int o = 16; o > 0; o >>= 1) v += __shfl_xor_sync(0xffffffffu, v, o);
    float r = rsqrtf(v * (1.f/256.f) + 1e-5f);

    const float* gp = g_gate + (size_t)row*VD + h*DV;
    __nv_bfloat16* yh = g_yh + (size_t)row*VD + h*DV;
    __nv_bfloat16* yl = g_yl + (size_t)row*VD + h*DV;
    #pragma unroll
    for (int i = 0; i < 8; i++) {
        float y = gp[lane + 32*i] * (x[i] - mu) * r;
        __nv_bfloat16 hh = __float2bfloat16(y);
        yh[lane + 32*i] = hh;
        yl[lane + 32*i] = __float2bfloat16(y - __bfloat162float(hh));
    }
}

// ---------------- launch -----------------------------------------------------
extern "C" void kernel_launch(void* const* d_in, const int* in_sizes, int n_in,
                              void* d_out, int out_size)
{
    (void)in_sizes; (void)n_in; (void)out_size;
    const float* X     = (const float*)d_in[0];
    const float* Wqkv  = (const float*)d_in[1];
    const float* Wg    = (const float*)d_in[2];
    const float* Wproj = (const float*)d_in[3];
    const float* decay = (const float*)d_in[4];
    float* out = (float*)d_out;
    float* curr_kv = out + (size_t)ROWS * DM;

    float *qkv, *gate;
    __nv_bfloat16 *xh, *xl, *wqh, *wql, *wgh, *wgl, *wph, *wpl, *yh, *yl;
    __nv_bfloat16 *qth, *qtl, *kth, *ktl, *vsh, *vsl;
    cudaGetSymbolAddress((void**)&qkv,  g_qkv);
    cudaGetSymbolAddress((void**)&gate, g_gate);
    cudaGetSymbolAddress((void**)&xh,  g_xh);
    cudaGetSymbolAddress((void**)&xl,  g_xl);
    cudaGetSymbolAddress((void**)&wqh, g_wqh);
    cudaGetSymbolAddress((void**)&wql, g_wql);
    cudaGetSymbolAddress((void**)&wgh, g_wgh);
    cudaGetSymbolAddress((void**)&wgl, g_wgl);
    cudaGetSymbolAddress((void**)&wph, g_wph);
    cudaGetSymbolAddress((void**)&wpl, g_wpl);
    cudaGetSymbolAddress((void**)&yh,  g_yh);
    cudaGetSymbolAddress((void**)&yl,  g_yl);
    cudaGetSymbolAddress((void**)&qth, g_qth);
    cudaGetSymbolAddress((void**)&qtl, g_qtl);
    cudaGetSymbolAddress((void**)&kth, g_kth);
    cudaGetSymbolAddress((void**)&ktl, g_ktl);
    cudaGetSymbolAddress((void**)&vsh, g_vsh);
    cudaGetSymbolAddress((void**)&vsl, g_vsl);

    cudaFuncSetAttribute(gemm_mma,   cudaFuncAttributeMaxDynamicSharedMemorySize, SMEM_GEMM);
    cudaFuncSetAttribute(pass_a_mma, cudaFuncAttributeMaxDynamicSharedMemorySize, PA_SMEM);
    cudaFuncSetAttribute(pass_b_mma, cudaFuncAttributeMaxDynamicSharedMemorySize, PB_SMEM);

    // 0) split/transpose GEMM operands to bf16 hi/lo
    {
        size_t n4 = (size_t)ROWS * DM / 4;
        split_kernel<<<(unsigned)((n4 + 255)/256), 256>>>((const float4*)X, xh, xl, n4);
    }
    tsplit_kernel<<<dim3(QKVC/32, DM/32), dim3(32,8)>>>(Wqkv,  wqh, wql, DM, QKVC);
    tsplit_kernel<<<dim3(VD/32,   DM/32), dim3(32,8)>>>(Wg,    wgh, wgl, DM, VD);
    tsplit_kernel<<<dim3(DM/32,   VD/32), dim3(32,8)>>>(Wproj, wph, wpl, VD, DM);

    // 1) QKV = X @ W_qkv ; 2) gate = silu(X @ W_g)
    gemm_mma<<<dim3(QKVC/BN, ROWS/BM), 256, SMEM_GEMM>>>(xh, xl, wqh, wql, qkv, ROWS, QKVC, DM, 0);
    gemm_mma<<<dim3(VD/BN, ROWS/BM), 256, SMEM_GEMM>>>(xh, xl, wgh, wgl, gate, ROWS, VD, DM, 1);

    // 3) rotary + decay fold + split; v split
    rotary_split<<<dim3(ROWS, 2), 256>>>(qkv, qth, qtl, kth, ktl, decay);
    v_split<<<dim3(ROWS, 2), 256>>>(qkv, vsh, vsl);

    // 4) per-chunk KV^T contributions (tensor)
    pass_a_mma<<<32*NCHUNK, 256, PA_SMEM>>>(kth, ktl, vsh, vsl, decay);
    // 5) state scan -> S_in^T hi/lo + curr_kv
    scan_k<<<32*128, 256>>>(curr_kv, decay);
    // 6) retention output (tensor)
    pass_b_mma<<<32*NCHUNK, 256, PB_SMEM>>>(qth, qtl, kth, ktl, vsh, vsl, decay);
    // 7) groupnorm + gate -> split-bf16 Y
    norm_gate<<<ROWS, 256>>>();
    // 8) proj_out = Y @ W_proj
    gemm_mma<<<dim3(DM/BN, ROWS/BM), 256, SMEM_GEMM>>>(yh, yl, wph, wpl, out, ROWS, DM, VD, 0);
}